// round 13
// baseline (speedup 1.0000x reference)
#include <cuda_runtime.h>
#include <cstdint>

#define LL 1024
#define DD 128
#define BQ 32
#define NT 512

#define S_FLOATS   (BQ * LL)        // 32768 floats = 128 KB
#define TILE_WORDS (128 * 132)      // [128 rows][33 float4] padded tile = 66 KB
#define Q_FLOATS   (BQ * DD)        // 16 KB
#define SMEM_BYTES ((S_FLOATS + TILE_WORDS + Q_FLOATS) * 4)   // 215040

typedef unsigned long long ull;

__device__ __forceinline__ ull pk2(float lo, float hi) {
    ull r; asm("mov.b64 %0, {%1, %2};" : "=l"(r) : "f"(lo), "f"(hi)); return r;
}
__device__ __forceinline__ float2 up2(ull v) {
    float2 r; asm("mov.b64 {%0, %1}, %2;" : "=f"(r.x), "=f"(r.y) : "l"(v)); return r;
}
__device__ __forceinline__ void fma2(ull &a, ull x, ull y) {
    asm("fma.rn.f32x2 %0, %1, %2, %0;" : "+l"(a) : "l"(x), "l"(y));
}

__global__ __launch_bounds__(NT, 1)
void attn_neg_kernel(const float* __restrict__ Qg, const float* __restrict__ Kg,
                     const float* __restrict__ Vg, const float* __restrict__ scp,
                     const float* __restrict__ kg, float* __restrict__ outg)
{
    extern __shared__ float smem[];
    float*  S   = smem;                                     // [BQ][LL]
    float*  Tl  = smem + S_FLOATS;                          // K/V tile [128][132]
    float4* Qs4 = (float4*)(smem + S_FLOATS + TILE_WORDS);  // [BQ][32]

    const int tid = threadIdx.x, warp = tid >> 5, lane = tid & 31;
    const int b = blockIdx.y, q0 = blockIdx.x * BQ;
    const float negscale = -scp[0];

    // ---- stage Q [32 q][32 f4] ----
    {
        const float4* Qg4 = (const float4*)(Qg + ((size_t)b * LL + q0) * DD);
        #pragma unroll
        for (int i = 0; i < 2; i++) Qs4[tid + NT * i] = Qg4[tid + NT * i];
    }

    // ============ Phase 1: S = -scale * Q @ K^T (d-packed fma2) ============
    // warp w: q-group (w>>2)*8 (8 rows), k-quarter (w&3)*32; lane owns k0.
    {
        const float4* Kgl = (const float4*)(Kg + (size_t)b * LL * DD);
        float4* Kt4 = (float4*)Tl;                    // [128 k][33 f4]
        const int qg = (warp >> 2) * 8;
        const int k0 = (warp & 3) * 32 + lane;

        float4 buf[8];
        #pragma unroll
        for (int i = 0; i < 8; i++) buf[i] = Kgl[tid + NT * i];

        for (int kt = 0; kt < 8; kt++) {
            __syncthreads();
            #pragma unroll
            for (int i = 0; i < 8; i++) {
                int idx = tid + NT * i;
                Kt4[(idx >> 5) * 33 + (idx & 31)] = buf[i];
            }
            __syncthreads();
            if (kt < 7) {
                #pragma unroll
                for (int i = 0; i < 8; i++)
                    buf[i] = Kgl[(kt + 1) * 4096 + tid + NT * i];
            }

            ull acc[8];
            #pragma unroll
            for (int i = 0; i < 8; i++) acc[i] = 0ull;

            #pragma unroll 4
            for (int d4 = 0; d4 < 32; d4++) {
                float4 ka = Kt4[k0 * 33 + d4];        // lane-varying, conflict-free
                ull ka01 = pk2(ka.x, ka.y), ka23 = pk2(ka.z, ka.w);  // adjacent: free
                #pragma unroll
                for (int i = 0; i < 8; i++) {
                    float4 qv = Qs4[(qg + i) * 32 + d4];             // broadcast
                    ull q01 = pk2(qv.x, qv.y), q23 = pk2(qv.z, qv.w);
                    fma2(acc[i], q01, ka01);
                    fma2(acc[i], q23, ka23);
                }
            }
            #pragma unroll
            for (int i = 0; i < 8; i++) {
                float2 a = up2(acc[i]);
                S[(qg + i) * LL + kt * 128 + k0] = (a.x + a.y) * negscale;
            }
        }
    }
    __syncthreads();

    // ============ Phase 2: beta = softmax(-softmax(S) * kg) ============
    // t = -p*kg in [-1,0] -> second max pass skipped (m2 = 0). 2 rows/warp.
    #pragma unroll 1
    for (int r = 0; r < 2; r++) {
        const int q = warp * 2 + r;
        float4* Srow4 = (float4*)(S + q * LL);
        const float4* kg4 = (const float4*)(kg + ((size_t)b * LL + q0 + q) * LL);

        float m1 = -1e30f;
        #pragma unroll
        for (int i = 0; i < 8; i++) {
            float4 s = Srow4[lane + 32 * i];
            m1 = fmaxf(m1, fmaxf(fmaxf(s.x, s.y), fmaxf(s.z, s.w)));
        }
        #pragma unroll
        for (int o = 16; o; o >>= 1) m1 = fmaxf(m1, __shfl_xor_sync(~0u, m1, o));

        float z1 = 0.f;
        #pragma unroll
        for (int i = 0; i < 8; i++) {
            float4 s = Srow4[lane + 32 * i];
            z1 += __expf(s.x - m1) + __expf(s.y - m1) + __expf(s.z - m1) + __expf(s.w - m1);
        }
        #pragma unroll
        for (int o = 16; o; o >>= 1) z1 += __shfl_xor_sync(~0u, z1, o);
        const float inv1 = 1.0f / z1;

        float z2 = 0.f;
        #pragma unroll
        for (int i = 0; i < 8; i++) {
            float4 s = Srow4[lane + 32 * i];
            float4 g = kg4[lane + 32 * i];
            float4 e;
            e.x = __expf(-__expf(s.x - m1) * inv1 * g.x);
            e.y = __expf(-__expf(s.y - m1) * inv1 * g.y);
            e.z = __expf(-__expf(s.z - m1) * inv1 * g.z);
            e.w = __expf(-__expf(s.w - m1) * inv1 * g.w);
            Srow4[lane + 32 * i] = e;
            z2 += e.x + e.y + e.z + e.w;
        }
        #pragma unroll
        for (int o = 16; o; o >>= 1) z2 += __shfl_xor_sync(~0u, z2, o);
        const float inv2 = 1.0f / z2;
        #pragma unroll
        for (int i = 0; i < 8; i++) {
            float4 e = Srow4[lane + 32 * i];
            e.x *= inv2; e.y *= inv2; e.z *= inv2; e.w *= inv2;
            Srow4[lane + 32 * i] = e;
        }
    }

    // ============ Phase 3: out = beta @ V (k-pair packed, coalesced V) ============
    // warp w: q-group (w>>1)*4 (4 rows), d-half (w&1)*64; lane owns f2 at d0.
    // V staged row-major [k][33 f4] (same coalesced pattern as K). beta pairs
    // come free from S float4 broadcasts; V k-pairs via a 2x2 reg transpose.
    {
        const float4* Vgl = (const float4*)(Vg + (size_t)b * LL * DD);
        float4* Vt4 = (float4*)Tl;
        const int qg = (warp >> 1) * 4;
        const int d0 = (warp & 1) * 64 + 2 * lane;      // f2 index d0, d0+1
        const int dOfs = (warp & 1) * 32 + lane;        // f2 offset within row

        float4 buf[8];
        #pragma unroll
        for (int i = 0; i < 8; i++) buf[i] = Vgl[tid + NT * i];

        ull acc[4][2];
        #pragma unroll
        for (int i = 0; i < 4; i++) { acc[i][0] = 0ull; acc[i][1] = 0ull; }

        for (int vt = 0; vt < 8; vt++) {
            __syncthreads();
            #pragma unroll
            for (int i = 0; i < 8; i++) {
                int idx = tid + NT * i;
                Vt4[(idx >> 5) * 33 + (idx & 31)] = buf[i];
            }
            __syncthreads();
            if (vt < 7) {
                #pragma unroll
                for (int i = 0; i < 8; i++)
                    buf[i] = Vgl[(vt + 1) * 4096 + tid + NT * i];
            }

            const float2* Vt2 = (const float2*)Tl;      // f2 row stride 66
            #pragma unroll 4
            for (int k4 = 0; k4 < 32; k4++) {           // 4 k rows per iter
                float2 v0 = Vt2[(4 * k4 + 0) * 66 + dOfs];
                float2 v1 = Vt2[(4 * k4 + 1) * 66 + dOfs];
                float2 v2 = Vt2[(4 * k4 + 2) * 66 + dOfs];
                float2 v3 = Vt2[(4 * k4 + 3) * 66 + dOfs];
                // 2x2 transposes: (k,k+1) pairs at fixed d — 4 real MOVs total
                ull u01_d0 = pk2(v0.x, v1.x), u01_d1 = pk2(v0.y, v1.y);
                ull u23_d0 = pk2(v2.x, v3.x), u23_d1 = pk2(v2.y, v3.y);
                #pragma unroll
                for (int i = 0; i < 4; i++) {
                    float4 bq = ((const float4*)(S + (qg + i) * LL + vt * 128))[k4]; // broadcast
                    ull b01 = pk2(bq.x, bq.y), b23 = pk2(bq.z, bq.w);   // adjacent: free
                    fma2(acc[i][0], b01, u01_d0);  fma2(acc[i][1], b01, u01_d1);
                    fma2(acc[i][0], b23, u23_d0);  fma2(acc[i][1], b23, u23_d1);
                }
            }
        }

        float* outp = outg + ((size_t)b * LL + q0) * DD;
        #pragma unroll
        for (int i = 0; i < 4; i++) {
            float2 a0 = up2(acc[i][0]), a1 = up2(acc[i][1]);
            float2 o; o.x = a0.x + a0.y; o.y = a1.x + a1.y;
            *(float2*)(outp + (qg + i) * DD + d0) = o;
        }
    }
}

extern "C" void kernel_launch(void* const* d_in, const int* in_sizes, int n_in,
                              void* d_out, int out_size) {
    const float* Q  = (const float*)d_in[0];
    const float* K  = (const float*)d_in[1];
    const float* V  = (const float*)d_in[2];
    const float* sc = (const float*)d_in[3];
    const float* kg = (const float*)d_in[4];
    float* out = (float*)d_out;
    (void)in_sizes; (void)n_in; (void)out_size;

    cudaFuncSetAttribute(attn_neg_kernel,
                         cudaFuncAttributeMaxDynamicSharedMemorySize, SMEM_BYTES);
    dim3 grid(LL / BQ, 32);
    attn_neg_kernel<<<grid, NT, SMEM_BYTES>>>(Q, K, V, sc, kg, out);
}

// round 14
// speedup vs baseline: 1.7888x; 1.7888x over previous
#include <cuda_runtime.h>
#include <cstdint>

#define LL 1024
#define NT 512
#define S_STR 1032
#define KH_O 33024
#define KL_O 41728
#define QH_O 50432
#define QL_O 52608
#define SM_W 54784
#define VB_O 33024
#define VTH_O 41472
#define VTL_O 46208
#define SMEM_BYTES (SM_W * 4)

__device__ __forceinline__ unsigned pkbf(float lo, float hi) {
    unsigned r; asm("cvt.rn.bf16x2.f32 %0, %1, %2;" : "=r"(r) : "f"(hi), "f"(lo)); return r;
}
__device__ __forceinline__ float lof(unsigned w) { return __uint_as_float(w << 16); }
__device__ __forceinline__ float hif(unsigned w) { return __uint_as_float(w & 0xffff0000u); }
__device__ __forceinline__ void cvt4(float4 f, unsigned &h0, unsigned &h1,
                                     unsigned &l0, unsigned &l1) {
    h0 = pkbf(f.x, f.y); h1 = pkbf(f.z, f.w);
    l0 = pkbf(f.x - lof(h0), f.y - hif(h0));
    l1 = pkbf(f.z - lof(h1), f.w - hif(h1));
}
__device__ __forceinline__ void mma(float* c, const unsigned* a, unsigned b0, unsigned b1) {
    asm("mma.sync.aligned.m16n8k16.row.col.f32.bf16.bf16.f32 "
        "{%0,%1,%2,%3},{%4,%5,%6,%7},{%8,%9},{%0,%1,%2,%3};"
        : "+f"(c[0]), "+f"(c[1]), "+f"(c[2]), "+f"(c[3])
        : "r"(a[0]), "r"(a[1]), "r"(a[2]), "r"(a[3]), "r"(b0), "r"(b1));
}

__global__ __launch_bounds__(NT, 1)
void attn_neg_kernel(const float* __restrict__ Qg, const float* __restrict__ Kg,
                     const float* __restrict__ Vg, const float* __restrict__ scp,
                     const float* __restrict__ kg, float* __restrict__ outg)
{
    extern __shared__ unsigned smw[];
    float* smf = (float*)smw;
    const int tid = threadIdx.x, warp = tid >> 5, lane = tid & 31;
    const int g = lane >> 2, t = lane & 3;
    const int b = blockIdx.y, q0 = blockIdx.x * 32;
    const int mh = warp >> 3, ng = warp & 7, qb = mh * 16;
    const float ns = -scp[0];

    // ---- stage Q packed hi/lo (words along d) ----
    {
        const float4* Qg4 = (const float4*)(Qg + ((size_t)b * LL + q0) * 128);
        #pragma unroll
        for (int i = 0; i < 2; i++) {
            int idx = tid + NT * i, row = idx >> 5, c4 = idx & 31;
            unsigned h0, h1, l0, l1; cvt4(Qg4[idx], h0, h1, l0, l1);
            *(uint2*)(smw + QH_O + row * 68 + 2 * c4) = make_uint2(h0, h1);
            *(uint2*)(smw + QL_O + row * 68 + 2 * c4) = make_uint2(l0, l1);
        }
    }

    // ================= Phase 1: S = -scale * Q @ K^T =================
    {
        const float4* Kgl = (const float4*)(Kg + (size_t)b * LL * 128);
        float4 buf[8];
        #pragma unroll
        for (int i = 0; i < 8; i++) buf[i] = Kgl[tid + NT * i];

        for (int kt = 0; kt < 8; kt++) {
            __syncthreads();
            #pragma unroll
            for (int i = 0; i < 8; i++) {
                int idx = tid + NT * i, row = idx >> 5, c4 = idx & 31;
                unsigned h0, h1, l0, l1; cvt4(buf[i], h0, h1, l0, l1);
                *(uint2*)(smw + KH_O + row * 68 + 2 * c4) = make_uint2(h0, h1);
                *(uint2*)(smw + KL_O + row * 68 + 2 * c4) = make_uint2(l0, l1);
            }
            __syncthreads();
            if (kt < 7) {
                #pragma unroll
                for (int i = 0; i < 8; i++) buf[i] = Kgl[(kt + 1) * 4096 + tid + NT * i];
            }

            float c[2][4] = {};
            #pragma unroll
            for (int ks = 0; ks < 8; ks++) {
                int qa = QH_O + (qb + g) * 68 + ks * 8 + t;
                unsigned ah[4] = { smw[qa], smw[qa + 544], smw[qa + 4], smw[qa + 548] };
                unsigned al[4] = { smw[qa + 2176], smw[qa + 2720], smw[qa + 2180], smw[qa + 2724] };
                #pragma unroll
                for (int nt = 0; nt < 2; nt++) {
                    int ba = KH_O + (ng * 16 + nt * 8 + g) * 68 + ks * 8 + t;
                    unsigned bh0 = smw[ba], bh1 = smw[ba + 4];
                    unsigned bl0 = smw[ba + 8704], bl1 = smw[ba + 8708];
                    mma(c[nt], ah, bh0, bh1);
                    mma(c[nt], ah, bl0, bl1);
                    mma(c[nt], al, bh0, bh1);
                }
            }
            #pragma unroll
            for (int nt = 0; nt < 2; nt++) {
                float* p = smf + (qb + g) * S_STR + kt * 128 + ng * 16 + nt * 8 + 2 * t;
                *(float2*)p = make_float2(c[nt][0] * ns, c[nt][1] * ns);
                *(float2*)(p + 8 * S_STR) = make_float2(c[nt][2] * ns, c[nt][3] * ns);
            }
        }
    }
    __syncthreads();

    // ===== Phase 2: beta = softmax(-softmax(S)*kg); pack hi/lo in place =====
    // t2 = -p*kg in [-1,0] -> second max pass skipped (m2 = 0). 2 rows/warp.
    #pragma unroll 1
    for (int r = 0; r < 2; r++) {
        const int q = warp * 2 + r;
        float4* Srow4 = (float4*)(smf + q * S_STR);
        const float4* kg4 = (const float4*)(kg + ((size_t)b * LL + q0 + q) * LL);

        float m1 = -1e30f;
        #pragma unroll
        for (int i = 0; i < 8; i++) {
            float4 s = Srow4[lane + 32 * i];
            m1 = fmaxf(m1, fmaxf(fmaxf(s.x, s.y), fmaxf(s.z, s.w)));
        }
        #pragma unroll
        for (int o = 16; o; o >>= 1) m1 = fmaxf(m1, __shfl_xor_sync(~0u, m1, o));

        float z1 = 0.f;
        #pragma unroll
        for (int i = 0; i < 8; i++) {
            float4 s = Srow4[lane + 32 * i];
            z1 += __expf(s.x - m1) + __expf(s.y - m1) + __expf(s.z - m1) + __expf(s.w - m1);
        }
        #pragma unroll
        for (int o = 16; o; o >>= 1) z1 += __shfl_xor_sync(~0u, z1, o);
        const float inv1 = 1.0f / z1;

        float z2 = 0.f;
        #pragma unroll
        for (int i = 0; i < 8; i++) {
            float4 s = Srow4[lane + 32 * i];
            float4 gg = kg4[lane + 32 * i];
            float4 e;
            e.x = __expf(-__expf(s.x - m1) * inv1 * gg.x);
            e.y = __expf(-__expf(s.y - m1) * inv1 * gg.y);
            e.z = __expf(-__expf(s.z - m1) * inv1 * gg.z);
            e.w = __expf(-__expf(s.w - m1) * inv1 * gg.w);
            Srow4[lane + 32 * i] = e;
            z2 += e.x + e.y + e.z + e.w;
        }
        #pragma unroll
        for (int o = 16; o; o >>= 1) z2 += __shfl_xor_sync(~0u, z2, o);
        const float inv2 = 1.0f / z2;
        #pragma unroll
        for (int i = 0; i < 8; i++) {
            float4 e = Srow4[lane + 32 * i];
            e.x *= inv2; e.y *= inv2; e.z *= inv2; e.w *= inv2;
            unsigned h01 = pkbf(e.x, e.y), h23 = pkbf(e.z, e.w);
            unsigned l01 = pkbf(e.x - lof(h01), e.y - hif(h01));
            unsigned l23 = pkbf(e.z - lof(h23), e.w - hif(h23));
            ((uint4*)Srow4)[lane + 32 * i] = make_uint4(h01, h23, l01, l23);
        }
    }
    __syncthreads();

    // ================= Phase 3: out = beta @ V =================
    {
        const float4* Vgl = (const float4*)(Vg + (size_t)b * LL * 128);
        float4 vbuf[4];
        #pragma unroll
        for (int i = 0; i < 4; i++) vbuf[i] = Vgl[tid + NT * i];

        const int dT = tid >> 2, bs = tid & 3;   // transpose roles
        float c[2][4] = {};

        for (int vt = 0; vt < 16; vt++) {
            __syncthreads();
            #pragma unroll
            for (int i = 0; i < 4; i++) {
                int idx = tid + NT * i, row = idx >> 5, c4 = idx & 31;
                *(float4*)(smf + VB_O + row * 132 + 4 * c4) = vbuf[i];
            }
            __syncthreads();
            if (vt < 15) {
                #pragma unroll
                for (int i = 0; i < 4; i++) vbuf[i] = Vgl[(vt + 1) * 2048 + tid + NT * i];
            }
            #pragma unroll
            for (int j = 0; j < 8; j++) {        // transpose+cvt: conflict-free
                int k2 = bs + 4 * j;
                float e0 = smf[VB_O + 2 * k2 * 132 + dT];
                float e1 = smf[VB_O + (2 * k2 + 1) * 132 + dT];
                unsigned h = pkbf(e0, e1);
                unsigned l = pkbf(e0 - lof(h), e1 - hif(h));
                smw[VTH_O + dT * 37 + k2] = h;
                smw[VTL_O + dT * 37 + k2] = l;
            }
            __syncthreads();

            #pragma unroll
            for (int ks = 0; ks < 4; ks++) {
                int G = vt * 4 + ks;
                int a0 = (qb + g) * S_STR + G * 16 + ((t >> 1) << 2) + (t & 1);
                unsigned ah[4] = { smw[a0], smw[a0 + 8 * S_STR],
                                   smw[a0 + 8], smw[a0 + 8 * S_STR + 8] };
                unsigned al[4] = { smw[a0 + 2], smw[a0 + 8 * S_STR + 2],
                                   smw[a0 + 10], smw[a0 + 8 * S_STR + 10] };
                #pragma unroll
                for (int nt = 0; nt < 2; nt++) {
                    int ba = VTH_O + (ng * 16 + nt * 8 + g) * 37 + ks * 8 + t;
                    unsigned bh0 = smw[ba], bh1 = smw[ba + 4];
                    unsigned bl0 = smw[ba + 4736], bl1 = smw[ba + 4740];
                    mma(c[nt], ah, bh0, bh1);
                    mma(c[nt], ah, bl0, bl1);
                    mma(c[nt], al, bh0, bh1);
                }
            }
        }

        float* op = outg + ((size_t)b * LL + q0 + qb + g) * 128 + ng * 16 + 2 * t;
        #pragma unroll
        for (int nt = 0; nt < 2; nt++) {
            *(float2*)(op + nt * 8) = make_float2(c[nt][0], c[nt][1]);
            *(float2*)(op + nt * 8 + 8 * 128) = make_float2(c[nt][2], c[nt][3]);
        }
    }
}

extern "C" void kernel_launch(void* const* d_in, const int* in_sizes, int n_in,
                              void* d_out, int out_size) {
    const float* Q  = (const float*)d_in[0];
    const float* K  = (const float*)d_in[1];
    const float* V  = (const float*)d_in[2];
    const float* sc = (const float*)d_in[3];
    const float* kgp = (const float*)d_in[4];
    float* out = (float*)d_out;
    (void)in_sizes; (void)n_in; (void)out_size;

    cudaFuncSetAttribute(attn_neg_kernel,
                         cudaFuncAttributeMaxDynamicSharedMemorySize, SMEM_BYTES);
    dim3 grid(LL / 32, 32);
    attn_neg_kernel<<<grid, NT, SMEM_BYTES>>>(Q, K, V, sc, kgp, out);
}